// round 10
// baseline (speedup 1.0000x reference)
#include <cuda_runtime.h>
#include <cuda_bf16.h>
#include <mma.h>
#include <math.h>

using namespace nvcuda;

#define NROWS 65536
#define DIM   256
#define KCB   1024

#define OFF_LOSS 0
#define OFF_Q    1
#define OFF_PERP (1 + NROWS*DIM)
#define OFF_EMB  (OFF_PERP + 1)
#define OFF_CS   (OFF_EMB + KCB*DIM)
#define OFF_EMA  (OFF_CS + KCB)

__device__ float  g_A[NROWS];
__device__ float  g_C[KCB];
__device__ int    g_idx[NROWS];
__device__ int    g_cand[NROWS*6];
__device__ float  g_counts[KCB];
__device__ float  g_dw[KCB*DIM];
__device__ float  g_cs[KCB];
__device__ double g_lp[2048];

__device__ __align__(16) __nv_bfloat16 g_xb[NROWS*DIM];
__device__ __align__(16) __nv_bfloat16 g_wb[KCB*DIM];

__device__ __forceinline__ unsigned smem_u32(const void* p) {
    unsigned a;
    asm("{ .reg .u64 t; cvta.to.shared.u64 t, %1; cvt.u32.u64 %0, t; }" : "=r"(a) : "l"(p));
    return a;
}
__device__ __forceinline__ int dless(float da, int ia, float db, int ib) {
    return (da < db) || (da == db && ia < ib);
}
#define CP_ASYNC16(dst, src) asm volatile("cp.async.cg.shared.global [%0], [%1], 16;" :: "r"(dst), "l"(src) : "memory")
#define CP_COMMIT()          asm volatile("cp.async.commit_group;" ::: "memory")
#define CP_WAIT(n)           asm volatile("cp.async.wait_group %0;" :: "n"(n) : "memory")

// ---------------- bf16 cast ----------------
__global__ __launch_bounds__(256) void k_cast(const float* __restrict__ s, int n4,
                                              __nv_bfloat16* __restrict__ d0) {
    int i = blockIdx.x * 256 + threadIdx.x;
    if (i >= n4) return;
    float4 v = ((const float4*)s)[i];
    ushort4 o0;
    o0.x = __bfloat16_as_ushort(__float2bfloat16_rn(v.x));
    o0.y = __bfloat16_as_ushort(__float2bfloat16_rn(v.y));
    o0.z = __bfloat16_as_ushort(__float2bfloat16_rn(v.z));
    o0.w = __bfloat16_as_ushort(__float2bfloat16_rn(v.w));
    ((ushort4*)d0)[i] = o0;
}

// ---- row squared norms (fp64-accumulated) ----
__global__ __launch_bounds__(256) void k_rownorm(const float* __restrict__ src,
                                                 int nrows, int which) {
    int wd = threadIdx.x >> 5, l = threadIdx.x & 31;
    int row = blockIdx.x * 8 + wd;
    if (row >= nrows) return;
    const float4* r4 = (const float4*)(src + (size_t)row * DIM);
    float4 a = r4[l], b = r4[l + 32];
    double s = (double)a.x*a.x + (double)a.y*a.y + (double)a.z*a.z + (double)a.w*a.w
             + (double)b.x*b.x + (double)b.y*b.y + (double)b.z*b.z + (double)b.w*b.w;
#pragma unroll
    for (int o = 16; o; o >>= 1) s += __shfl_down_sync(0xffffffffu, s, o);
    if (!l) { if (which) g_C[row] = (float)s; else g_A[row] = (float)s; }
}

// ---------------- wmma distance GEMM -> top-3 candidates per half ----------------
#define LDA 264
#define LDB 40
#define AS_BYTES (128*LDA*2)
#define BS_BYTES (128*LDB*2)
#define OFF_AS   0
#define OFF_BS   (AS_BYTES)
#define OFF_SCR  (OFF_BS + 3*BS_BYTES)
#define SMEM_TOT (OFF_SCR + 8*1280)

// chunk cg in [0,64): ct = (cg>>3)*128 codes, kc = cg&7 (k-offset kc*32)
__device__ __forceinline__ void prefetch_b(char* smem, int tid, int cg) {
    int ct = (cg >> 3) * 128, kc = cg & 7;
    int code = tid >> 1, half = tid & 1;
    const __nv_bfloat16* src = g_wb + (size_t)(ct + code) * DIM + kc * 32 + half * 16;
    unsigned dst = smem_u32(smem + OFF_BS + (cg % 3) * BS_BYTES + (code * LDB + half * 16) * 2);
    CP_ASYNC16(dst, src);
    CP_ASYNC16(dst + 16, src + 8);
    CP_COMMIT();
}

__global__ __launch_bounds__(256,2) void k_mma_cand() {
    extern __shared__ char smem[];
    __nv_bfloat16* As = (__nv_bfloat16*)(smem + OFF_AS);
    int tid = threadIdx.x, w = tid >> 5, lane = tid & 31;
    int rowBase = blockIdx.x * 128;
    int rw = w >> 1, cw = w & 1;

    // A resident: 128 rows x 256 K bf16
    for (int u = tid; u < 128 * 32; u += 256) {
        int r = u >> 5, c8 = u & 31;
        *(uint4*)(As + r * LDA + c8 * 8) =
            *(const uint4*)(g_xb + (size_t)(rowBase + r) * DIM + c8 * 8);
    }
    // prologue prefetch (chunks 0,1) before the A-barrier to overlap
    prefetch_b(smem, tid, 0);
    prefetch_b(smem, tid, 1);
    __syncthreads();

    int r_local = lane >> 1;
    int csub = (lane & 1) * 8;
    float Ar[2];
    Ar[0] = g_A[rowBase + rw * 32 + r_local];
    Ar[1] = g_A[rowBase + rw * 32 + 16 + r_local];
    float tD[2][3]; int tI[2][3];
#pragma unroll
    for (int fr = 0; fr < 2; fr++)
#pragma unroll
        for (int s = 0; s < 3; s++) { tD[fr][s] = 3.4e38f; tI[fr][s] = 0x7ffffff0 + s; }

    wmma::fragment<wmma::accumulator, 16, 16, 16, float> acc[2][4];

    for (int cg = 0; cg < 64; cg++) {
        int kc = cg & 7;
        if (kc == 0) {
#pragma unroll
            for (int fr = 0; fr < 2; fr++)
#pragma unroll
                for (int fc = 0; fc < 4; fc++) wmma::fill_fragment(acc[fr][fc], 0.0f);
        }
        if (cg >= 62) { CP_WAIT(0); } else { CP_WAIT(1); }
        __syncthreads();
        if (cg + 2 < 64) prefetch_b(smem, tid, cg + 2);

        const __nv_bfloat16* Bs = (const __nv_bfloat16*)(smem + OFF_BS + (cg % 3) * BS_BYTES);
        int acol = kc * 32;
#pragma unroll
        for (int ks = 0; ks < 2; ks++) {
            wmma::fragment<wmma::matrix_a, 16, 16, 16, __nv_bfloat16, wmma::row_major> af[2];
            wmma::fragment<wmma::matrix_b, 16, 16, 16, __nv_bfloat16, wmma::col_major> bf[4];
#pragma unroll
            for (int fr = 0; fr < 2; fr++)
                wmma::load_matrix_sync(af[fr], As + (rw * 32 + fr * 16) * LDA + acol + ks * 16, LDA);
#pragma unroll
            for (int fc = 0; fc < 4; fc++)
                wmma::load_matrix_sync(bf[fc], Bs + (cw * 64 + fc * 16) * LDB + ks * 16, LDB);
#pragma unroll
            for (int fr = 0; fr < 2; fr++)
#pragma unroll
                for (int fc = 0; fc < 4; fc++)
                    wmma::mma_sync(acc[fr][fc], af[fr], bf[fc], acc[fr][fc]);
        }

        if (kc == 7) {
            // epilogue for this 128-code tile: approx distances -> per-thread top-3
            int ct = (cg >> 3) * 128;
            float* scr = (float*)(smem + OFF_SCR + w * 1280);
#pragma unroll
            for (int fr = 0; fr < 2; fr++)
#pragma unroll
                for (int fc = 0; fc < 4; fc++) {
                    wmma::store_matrix_sync(scr, acc[fr][fc], 20, wmma::mem_row_major);
                    __syncwarp();
                    int cbase = ct + cw * 64 + fc * 16 + csub;
#pragma unroll
                    for (int j = 0; j < 8; j++) {
                        float dot = scr[r_local * 20 + csub + j];
                        int code = cbase + j;
                        float d = __fadd_rn(__fsub_rn(Ar[fr], __fmul_rn(2.0f, dot)),
                                            __ldg(&g_C[code]));
                        if (dless(d, code, tD[fr][0], tI[fr][0])) {
                            tD[fr][2] = tD[fr][1]; tI[fr][2] = tI[fr][1];
                            tD[fr][1] = tD[fr][0]; tI[fr][1] = tI[fr][0];
                            tD[fr][0] = d; tI[fr][0] = code;
                        } else if (dless(d, code, tD[fr][1], tI[fr][1])) {
                            tD[fr][2] = tD[fr][1]; tI[fr][2] = tI[fr][1];
                            tD[fr][1] = d; tI[fr][1] = code;
                        } else if (dless(d, code, tD[fr][2], tI[fr][2])) {
                            tD[fr][2] = d; tI[fr][2] = code;
                        }
                    }
                    __syncwarp();
                }
        }
    }

    // merge lane pair (csub 0 & 8) -> top-3 per (row, half)
#pragma unroll
    for (int fr = 0; fr < 2; fr++) {
        float md[6]; int mi[6];
#pragma unroll
        for (int s = 0; s < 3; s++) {
            md[s] = tD[fr][s]; mi[s] = tI[fr][s];
            md[3 + s] = __shfl_xor_sync(0xffffffffu, tD[fr][s], 1);
            mi[3 + s] = __shfl_xor_sync(0xffffffffu, tI[fr][s], 1);
        }
#pragma unroll
        for (int p = 0; p < 3; p++)
#pragma unroll
            for (int q = p + 1; q < 6; q++)
                if (dless(md[q], mi[q], md[p], mi[p])) {
                    float td = md[p]; md[p] = md[q]; md[q] = td;
                    int   ti = mi[p]; mi[p] = mi[q]; mi[q] = ti;
                }
        if ((lane & 1) == 0) {
            int row = rowBase + rw * 32 + fr * 16 + r_local;
#pragma unroll
            for (int s = 0; s < 3; s++) g_cand[row * 6 + cw * 3 + s] = mi[s];
        }
    }
}

// ---------------- exact rescore (replicates R3 SIMT arithmetic) ----------------
__global__ __launch_bounds__(256) void k_rescore(const float* __restrict__ x,
                                                 const float* __restrict__ w) {
    int row = blockIdx.x * 256 + threadIdx.x;
    if (row >= NROWS) return;
    int c[6];
#pragma unroll
    for (int s = 0; s < 6; s++) c[s] = g_cand[row * 6 + s];
    const float4* xr = (const float4*)(x + (size_t)row * DIM);
    const float4* wr[6];
#pragma unroll
    for (int s = 0; s < 6; s++) wr[s] = (const float4*)(w + (size_t)c[s] * DIM);
    float dot[6] = {0.f, 0.f, 0.f, 0.f, 0.f, 0.f};
#pragma unroll 4
    for (int k4 = 0; k4 < 64; k4++) {
        float4 xv = xr[k4];
#pragma unroll
        for (int s = 0; s < 6; s++) {
            float4 wv = wr[s][k4];
            dot[s] = __fmaf_rn(xv.x, wv.x, dot[s]);
            dot[s] = __fmaf_rn(xv.y, wv.y, dot[s]);
            dot[s] = __fmaf_rn(xv.z, wv.z, dot[s]);
            dot[s] = __fmaf_rn(xv.w, wv.w, dot[s]);
        }
    }
    float A = g_A[row];
    float bd = 3.4e38f; int bi = 0x7fffffff;
#pragma unroll
    for (int s = 0; s < 6; s++) {
        float d = __fadd_rn(__fsub_rn(A, __fmul_rn(2.0f, dot[s])), g_C[c[s]]);
        if (dless(d, c[s], bd, bi)) { bd = d; bi = c[s]; }
    }
    g_idx[row] = bi;
}

// ---- gather codebook, STE output, loss partials ----
__global__ __launch_bounds__(256) void k_quant(const float* __restrict__ x,
                                               const float* __restrict__ w,
                                               float* __restrict__ out) {
    __shared__ double sr[256];
    double ls = 0.0;
    int stride = gridDim.x * 256;
    for (int e4 = blockIdx.x*256 + threadIdx.x; e4 < NROWS*DIM/4; e4 += stride) {
        int row = e4 >> 6, c4 = e4 & 63;
        int k = g_idx[row];
        float4 xv = ((const float4*)x)[e4];
        float4 qv = ((const float4*)w)[k*64 + c4];
        float d0 = __fsub_rn(qv.x, xv.x), d1 = __fsub_rn(qv.y, xv.y);
        float d2 = __fsub_rn(qv.z, xv.z), d3 = __fsub_rn(qv.w, xv.w);
        float* o = out + OFF_Q + (size_t)e4*4;
        o[0] = __fadd_rn(xv.x, d0); o[1] = __fadd_rn(xv.y, d1);
        o[2] = __fadd_rn(xv.z, d2); o[3] = __fadd_rn(xv.w, d3);
        float s4 = __fmaf_rn(d0, d0, __fmaf_rn(d1, d1, __fmaf_rn(d2, d2, d3*d3)));
        ls += (double)s4;
    }
    sr[threadIdx.x] = ls;
    __syncthreads();
    for (int o = 128; o; o >>= 1) { if (threadIdx.x < o) sr[threadIdx.x] += sr[threadIdx.x + o]; __syncthreads(); }
    if (!threadIdx.x) g_lp[blockIdx.x] = sr[0];
}

// ---- deterministic per-code counts + dw ----
__global__ __launch_bounds__(256) void k_counts(const float* __restrict__ x) {
    __shared__ int list[4096];
    __shared__ int cnt;
    int k = blockIdx.x, d = threadIdx.x;
    float acc = 0.f; int total = 0;
    for (int base = 0; base < NROWS; base += 4096) {
        if (!threadIdx.x) cnt = 0;
        __syncthreads();
        for (int i = threadIdx.x; i < 4096; i += 256)
            if (g_idx[base + i] == k) list[atomicAdd(&cnt, 1)] = base + i;
        __syncthreads();
        int m = cnt;
        for (int j = 0; j < m; j++) acc += x[(size_t)list[j]*DIM + d];
        total += m;
        __syncthreads();
    }
    g_dw[k*DIM + d] = acc;
    if (!threadIdx.x) g_counts[k] = (float)total;
}

// ---- scalars ----
__global__ __launch_bounds__(256) void k_scalars(const float* __restrict__ ecs,
                                                 float* __restrict__ out) {
    __shared__ double sd[256];
    int t = threadIdx.x;
    double s = 0;
    for (int i = t; i < 2048; i += 256) s += g_lp[i];
    sd[t] = s; __syncthreads();
    for (int o = 128; o; o >>= 1) { if (t < o) sd[t] += sd[t + o]; __syncthreads(); }
    double loss = 0.25 * sd[0] / ((double)NROWS * DIM);
    double ns = 0;
    for (int k = t; k < KCB; k += 256) {
        float ncs = __fadd_rn(__fmul_rn(0.99f, ecs[k]), __fmul_rn(0.01f, g_counts[k]));
        out[OFF_CS + k] = ncs;
        ns += ncs;
    }
    __syncthreads(); sd[t] = ns; __syncthreads();
    for (int o = 128; o; o >>= 1) { if (t < o) sd[t] += sd[t + o]; __syncthreads(); }
    float nf = (float)sd[0];
    float denom = __fadd_rn(nf, (float)(1024.0 * 1e-5));
    for (int k = t; k < KCB; k += 256) {
        float ncs = out[OFF_CS + k];
        g_cs[k] = __fmul_rn(__fdiv_rn(__fadd_rn(ncs, 1e-5f), denom), nf);
    }
    double ps = 0;
    for (int k = t; k < KCB; k += 256) {
        double p = (double)g_counts[k] / (double)NROWS;
        ps += p * log(p + 1e-10);
    }
    __syncthreads(); sd[t] = ps; __syncthreads();
    for (int o = 128; o; o >>= 1) { if (t < o) sd[t] += sd[t + o]; __syncthreads(); }
    if (!t) { out[OFF_LOSS] = (float)loss; out[OFF_PERP] = (float)exp(-sd[0]); }
}

// ---- EMA codebook update ----
__global__ __launch_bounds__(256) void k_emb(const float* __restrict__ emaw,
                                             float* __restrict__ out) {
    int e = blockIdx.x*256 + threadIdx.x;
    if (e >= KCB*DIM) return;
    int k = e >> 8;
    float ne = __fadd_rn(__fmul_rn(0.99f, emaw[e]), __fmul_rn(0.01f, g_dw[e]));
    out[OFF_EMA + e] = ne;
    out[OFF_EMB + e] = __fdiv_rn(ne, g_cs[k]);
}

extern "C" void kernel_launch(void* const* d_in, const int* in_sizes, int n_in,
                              void* d_out, int out_size) {
    const float* x    = (const float*)d_in[0];
    const float* w    = (const float*)d_in[1];
    const float* ecs  = (const float*)d_in[2];
    const float* emaw = (const float*)d_in[3];
    float* out = (float*)d_out;

    cudaFuncSetAttribute(k_mma_cand,
        cudaFuncAttributeMaxDynamicSharedMemorySize, SMEM_TOT);

    __nv_bfloat16 *xb, *wb;
    cudaGetSymbolAddress((void**)&xb, g_xb);
    cudaGetSymbolAddress((void**)&wb, g_wb);

    k_cast<<<NROWS*DIM/4/256, 256>>>(x, NROWS*DIM/4, xb);
    k_cast<<<KCB*DIM/4/256,   256>>>(w, KCB*DIM/4,   wb);
    k_rownorm<<<NROWS/8, 256>>>(x, NROWS, 0);
    k_rownorm<<<KCB/8,   256>>>(w, KCB,   1);
    k_mma_cand<<<NROWS/128, 256, SMEM_TOT>>>();
    k_rescore<<<NROWS/256, 256>>>(x, w);
    k_quant<<<2048, 256>>>(x, w, out);
    k_counts<<<KCB, 256>>>(x);
    k_scalars<<<1, 256>>>(ecs, out);
    k_emb<<<KCB*DIM/256, 256>>>(emaw, out);
}

// round 11
// speedup vs baseline: 1.0653x; 1.0653x over previous
#include <cuda_runtime.h>
#include <cuda_bf16.h>
#include <mma.h>
#include <math.h>

using namespace nvcuda;

#define NROWS 65536
#define DIM   256
#define KCB   1024

#define OFF_LOSS 0
#define OFF_Q    1
#define OFF_PERP (1 + NROWS*DIM)
#define OFF_EMB  (OFF_PERP + 1)
#define OFF_CS   (OFF_EMB + KCB*DIM)
#define OFF_EMA  (OFF_CS + KCB)

__device__ float  g_A[NROWS];
__device__ float  g_C[KCB];
__device__ int    g_idx[NROWS];
__device__ int    g_cand[NROWS*6];
__device__ float  g_counts[KCB];
__device__ float  g_dw[KCB*DIM];
__device__ float  g_cs[KCB];
__device__ double g_lp[2048];
__device__ int    g_ccount[KCB];
__device__ int    g_cursor[KCB];
__device__ int    g_off[KCB];
__device__ int    g_rows[NROWS];

__device__ __align__(16) __nv_bfloat16 g_xb[NROWS*DIM];
__device__ __align__(16) __nv_bfloat16 g_wb[KCB*DIM];

__device__ __forceinline__ unsigned smem_u32(const void* p) {
    unsigned a;
    asm("{ .reg .u64 t; cvta.to.shared.u64 t, %1; cvt.u32.u64 %0, t; }" : "=r"(a) : "l"(p));
    return a;
}
__device__ __forceinline__ int dless(float da, int ia, float db, int ib) {
    return (da < db) || (da == db && ia < ib);
}
#define CP_ASYNC16(dst, src) asm volatile("cp.async.cg.shared.global [%0], [%1], 16;" :: "r"(dst), "l"(src) : "memory")
#define CP_COMMIT()          asm volatile("cp.async.commit_group;" ::: "memory")
#define CP_WAIT(n)           asm volatile("cp.async.wait_group %0;" :: "n"(n) : "memory")

// ---------------- bf16 cast ----------------
__global__ __launch_bounds__(256) void k_cast(const float* __restrict__ s, int n4,
                                              __nv_bfloat16* __restrict__ d0) {
    int i = blockIdx.x * 256 + threadIdx.x;
    if (i >= n4) return;
    float4 v = ((const float4*)s)[i];
    ushort4 o0;
    o0.x = __bfloat16_as_ushort(__float2bfloat16_rn(v.x));
    o0.y = __bfloat16_as_ushort(__float2bfloat16_rn(v.y));
    o0.z = __bfloat16_as_ushort(__float2bfloat16_rn(v.z));
    o0.w = __bfloat16_as_ushort(__float2bfloat16_rn(v.w));
    ((ushort4*)d0)[i] = o0;
}

// ---- both row-norm sets in ONE launch (keeps k_mma_cand in ncu's slot 4) ----
__global__ __launch_bounds__(256) void k_rownorm_both(const float* __restrict__ x,
                                                      const float* __restrict__ w) {
    int wd = threadIdx.x >> 5, l = threadIdx.x & 31;
    int b = blockIdx.x;
    const float* src; int row; int isC;
    if (b < NROWS/8) { row = b * 8 + wd; src = x; isC = 0; if (row >= NROWS) return; }
    else             { row = (b - NROWS/8) * 8 + wd; src = w; isC = 1; if (row >= KCB) return; }
    const float4* r4 = (const float4*)(src + (size_t)row * DIM);
    float4 a = r4[l], bb = r4[l + 32];
    double s = (double)a.x*a.x + (double)a.y*a.y + (double)a.z*a.z + (double)a.w*a.w
             + (double)bb.x*bb.x + (double)bb.y*bb.y + (double)bb.z*bb.z + (double)bb.w*bb.w;
#pragma unroll
    for (int o = 16; o; o >>= 1) s += __shfl_down_sync(0xffffffffu, s, o);
    if (!l) { if (isC) g_C[row] = (float)s; else g_A[row] = (float)s; }
}

// ---------------- wmma distance GEMM -> top-3 candidates per half (R9 verbatim) ----------------
#define LDA 264
#define LDB 40
#define AS_BYTES (128*LDA*2)
#define BS_BYTES (128*LDB*2)
#define OFF_AS   0
#define OFF_BS   (AS_BYTES)
#define OFF_SC   (OFF_BS + 2*BS_BYTES)
#define OFF_SCR  (OFF_SC + 4096)
#define SMEM_TOT (OFF_SCR + 8192)

__device__ __forceinline__ void prefetch_b(char* smem, int tid, int buf, int kc, int ct) {
    int code = tid >> 1, half = tid & 1;
    const __nv_bfloat16* src = g_wb + (size_t)(ct + code) * DIM + kc * 32 + half * 16;
    unsigned dst = smem_u32(smem + OFF_BS + buf * BS_BYTES + (code * LDB + half * 16) * 2);
    CP_ASYNC16(dst, src);
    CP_ASYNC16(dst + 16, src + 8);
    CP_COMMIT();
}

__global__ __launch_bounds__(256,2) void k_mma_cand() {
    extern __shared__ char smem[];
    __nv_bfloat16* As = (__nv_bfloat16*)(smem + OFF_AS);
    float* sC = (float*)(smem + OFF_SC);
    int tid = threadIdx.x, w = tid >> 5, lane = tid & 31;
    int rowBase = blockIdx.x * 128;
    int rw = w >> 1, cw = w & 1;

    for (int i = tid; i < KCB; i += 256) sC[i] = g_C[i];

    for (int u = tid; u < 128 * 32; u += 256) {
        int r = u >> 5, c8 = u & 31;
        *(uint4*)(As + r * LDA + c8 * 8) =
            *(const uint4*)(g_xb + (size_t)(rowBase + r) * DIM + c8 * 8);
    }
    __syncthreads();

    int r_local = lane >> 1;
    int csub = (lane & 1) * 8;
    float Ar[2];
    Ar[0] = g_A[rowBase + rw * 32 + r_local];
    Ar[1] = g_A[rowBase + rw * 32 + 16 + r_local];
    float tD[2][3]; int tI[2][3];
#pragma unroll
    for (int fr = 0; fr < 2; fr++)
#pragma unroll
        for (int s = 0; s < 3; s++) { tD[fr][s] = 3.4e38f; tI[fr][s] = 0x7ffffff0 + s; }

    for (int ct8 = 0; ct8 < 8; ct8++) {
        int ct = ct8 * 128;
        wmma::fragment<wmma::accumulator, 16, 16, 16, float> acc[2][4];
#pragma unroll
        for (int fr = 0; fr < 2; fr++)
#pragma unroll
            for (int fc = 0; fc < 4; fc++) wmma::fill_fragment(acc[fr][fc], 0.0f);

        prefetch_b(smem, tid, 0, 0, ct);
        for (int kc = 0; kc < 8; kc++) {
            if (kc + 1 < 8) { prefetch_b(smem, tid, (kc + 1) & 1, kc + 1, ct); CP_WAIT(1); }
            else            { CP_WAIT(0); }
            __syncthreads();
            const __nv_bfloat16* Bs = (const __nv_bfloat16*)(smem + OFF_BS + (kc & 1) * BS_BYTES);
            int acol = kc * 32;
#pragma unroll
            for (int ks = 0; ks < 2; ks++) {
                wmma::fragment<wmma::matrix_a, 16, 16, 16, __nv_bfloat16, wmma::row_major> af[2];
                wmma::fragment<wmma::matrix_b, 16, 16, 16, __nv_bfloat16, wmma::col_major> bf[4];
#pragma unroll
                for (int fr = 0; fr < 2; fr++)
                    wmma::load_matrix_sync(af[fr], As + (rw * 32 + fr * 16) * LDA + acol + ks * 16, LDA);
#pragma unroll
                for (int fc = 0; fc < 4; fc++)
                    wmma::load_matrix_sync(bf[fc], Bs + (cw * 64 + fc * 16) * LDB + ks * 16, LDB);
#pragma unroll
                for (int fr = 0; fr < 2; fr++)
#pragma unroll
                    for (int fc = 0; fc < 4; fc++)
                        wmma::mma_sync(acc[fr][fc], af[fr], bf[fc], acc[fr][fc]);
            }
            __syncthreads();
        }

        float* scr = (float*)(smem + OFF_SCR + w * 1024);
#pragma unroll
        for (int fr = 0; fr < 2; fr++)
#pragma unroll
            for (int fc = 0; fc < 4; fc++) {
                wmma::store_matrix_sync(scr, acc[fr][fc], 16, wmma::mem_row_major);
                __syncwarp();
                int cbase = ct + cw * 64 + fc * 16 + csub;
#pragma unroll
                for (int j = 0; j < 8; j++) {
                    float dot = scr[r_local * 16 + csub + j];
                    int code = cbase + j;
                    float d = __fadd_rn(__fsub_rn(Ar[fr], __fmul_rn(2.0f, dot)), sC[code]);
                    if (dless(d, code, tD[fr][0], tI[fr][0])) {
                        tD[fr][2] = tD[fr][1]; tI[fr][2] = tI[fr][1];
                        tD[fr][1] = tD[fr][0]; tI[fr][1] = tI[fr][0];
                        tD[fr][0] = d; tI[fr][0] = code;
                    } else if (dless(d, code, tD[fr][1], tI[fr][1])) {
                        tD[fr][2] = tD[fr][1]; tI[fr][2] = tI[fr][1];
                        tD[fr][1] = d; tI[fr][1] = code;
                    } else if (dless(d, code, tD[fr][2], tI[fr][2])) {
                        tD[fr][2] = d; tI[fr][2] = code;
                    }
                }
                __syncwarp();
            }
    }

#pragma unroll
    for (int fr = 0; fr < 2; fr++) {
        float md[6]; int mi[6];
#pragma unroll
        for (int s = 0; s < 3; s++) {
            md[s] = tD[fr][s]; mi[s] = tI[fr][s];
            md[3 + s] = __shfl_xor_sync(0xffffffffu, tD[fr][s], 1);
            mi[3 + s] = __shfl_xor_sync(0xffffffffu, tI[fr][s], 1);
        }
#pragma unroll
        for (int p = 0; p < 3; p++)
#pragma unroll
            for (int q = p + 1; q < 6; q++)
                if (dless(md[q], mi[q], md[p], mi[p])) {
                    float td = md[p]; md[p] = md[q]; md[q] = td;
                    int   ti = mi[p]; mi[p] = mi[q]; mi[q] = ti;
                }
        if ((lane & 1) == 0) {
            int row = rowBase + rw * 32 + fr * 16 + r_local;
#pragma unroll
            for (int s = 0; s < 3; s++) g_cand[row * 6 + cw * 3 + s] = mi[s];
        }
    }
}

// ---------------- exact rescore (replicates R3 SIMT arithmetic) + bucket-zero ----------------
__global__ __launch_bounds__(256) void k_rescore(const float* __restrict__ x,
                                                 const float* __restrict__ w) {
    int row = blockIdx.x * 256 + threadIdx.x;
    if (row >= NROWS) return;
    if (row < KCB) { g_ccount[row] = 0; g_cursor[row] = 0; }
    int c[6];
#pragma unroll
    for (int s = 0; s < 6; s++) c[s] = g_cand[row * 6 + s];
    const float4* xr = (const float4*)(x + (size_t)row * DIM);
    const float4* wr[6];
#pragma unroll
    for (int s = 0; s < 6; s++) wr[s] = (const float4*)(w + (size_t)c[s] * DIM);
    float dot[6] = {0.f, 0.f, 0.f, 0.f, 0.f, 0.f};
#pragma unroll 4
    for (int k4 = 0; k4 < 64; k4++) {
        float4 xv = xr[k4];
#pragma unroll
        for (int s = 0; s < 6; s++) {
            float4 wv = wr[s][k4];
            dot[s] = __fmaf_rn(xv.x, wv.x, dot[s]);
            dot[s] = __fmaf_rn(xv.y, wv.y, dot[s]);
            dot[s] = __fmaf_rn(xv.z, wv.z, dot[s]);
            dot[s] = __fmaf_rn(xv.w, wv.w, dot[s]);
        }
    }
    float A = g_A[row];
    float bd = 3.4e38f; int bi = 0x7fffffff;
#pragma unroll
    for (int s = 0; s < 6; s++) {
        float d = __fadd_rn(__fsub_rn(A, __fmul_rn(2.0f, dot[s])), g_C[c[s]]);
        if (dless(d, c[s], bd, bi)) { bd = d; bi = c[s]; }
    }
    g_idx[row] = bi;
}

// ---- bucket pipeline: histogram -> scan -> scatter -> dw gather ----
__global__ __launch_bounds__(256) void k_count() {
    int i = blockIdx.x * 256 + threadIdx.x;
    if (i < NROWS) atomicAdd(&g_ccount[g_idx[i]], 1);
}

__global__ __launch_bounds__(1024) void k_scan() {
    __shared__ int sh[1024];
    int t = threadIdx.x;
    int v = g_ccount[t];
    sh[t] = v;
    __syncthreads();
    int sum = v;
    for (int o = 1; o < 1024; o <<= 1) {
        int add = (t >= o) ? sh[t - o] : 0;
        __syncthreads();
        sh[t] = sum = sum + add;
        __syncthreads();
    }
    g_off[t] = sum - v;           // exclusive
    g_counts[t] = (float)v;
}

__global__ __launch_bounds__(256) void k_scatter() {
    int i = blockIdx.x * 256 + threadIdx.x;
    if (i >= NROWS) return;
    int k = g_idx[i];
    int pos = atomicAdd(&g_cursor[k], 1);
    g_rows[g_off[k] + pos] = i;
}

__global__ __launch_bounds__(256) void k_dw(const float* __restrict__ x) {
    int k = blockIdx.x, d = threadIdx.x;
    int off = g_off[k], m = g_ccount[k];
    float acc = 0.f;
    for (int j = 0; j < m; j++)
        acc += x[(size_t)g_rows[off + j] * DIM + d];
    g_dw[k * DIM + d] = acc;
}

// ---- gather codebook, STE output, loss partials ----
__global__ __launch_bounds__(256) void k_quant(const float* __restrict__ x,
                                               const float* __restrict__ w,
                                               float* __restrict__ out) {
    __shared__ double sr[256];
    double ls = 0.0;
    int stride = gridDim.x * 256;
    for (int e4 = blockIdx.x*256 + threadIdx.x; e4 < NROWS*DIM/4; e4 += stride) {
        int row = e4 >> 6, c4 = e4 & 63;
        int k = g_idx[row];
        float4 xv = ((const float4*)x)[e4];
        float4 qv = ((const float4*)w)[k*64 + c4];
        float d0 = __fsub_rn(qv.x, xv.x), d1 = __fsub_rn(qv.y, xv.y);
        float d2 = __fsub_rn(qv.z, xv.z), d3 = __fsub_rn(qv.w, xv.w);
        float* o = out + OFF_Q + (size_t)e4*4;
        o[0] = __fadd_rn(xv.x, d0); o[1] = __fadd_rn(xv.y, d1);
        o[2] = __fadd_rn(xv.z, d2); o[3] = __fadd_rn(xv.w, d3);
        float s4 = __fmaf_rn(d0, d0, __fmaf_rn(d1, d1, __fmaf_rn(d2, d2, d3*d3)));
        ls += (double)s4;
    }
    sr[threadIdx.x] = ls;
    __syncthreads();
    for (int o = 128; o; o >>= 1) { if (threadIdx.x < o) sr[threadIdx.x] += sr[threadIdx.x + o]; __syncthreads(); }
    if (!threadIdx.x) g_lp[blockIdx.x] = sr[0];
}

// ---- scalars ----
__global__ __launch_bounds__(256) void k_scalars(const float* __restrict__ ecs,
                                                 float* __restrict__ out) {
    __shared__ double sd[256];
    int t = threadIdx.x;
    double s = 0;
    for (int i = t; i < 2048; i += 256) s += g_lp[i];
    sd[t] = s; __syncthreads();
    for (int o = 128; o; o >>= 1) { if (t < o) sd[t] += sd[t + o]; __syncthreads(); }
    double loss = 0.25 * sd[0] / ((double)NROWS * DIM);
    double ns = 0;
    for (int k = t; k < KCB; k += 256) {
        float ncs = __fadd_rn(__fmul_rn(0.99f, ecs[k]), __fmul_rn(0.01f, g_counts[k]));
        out[OFF_CS + k] = ncs;
        ns += ncs;
    }
    __syncthreads(); sd[t] = ns; __syncthreads();
    for (int o = 128; o; o >>= 1) { if (t < o) sd[t] += sd[t + o]; __syncthreads(); }
    float nf = (float)sd[0];
    float denom = __fadd_rn(nf, (float)(1024.0 * 1e-5));
    for (int k = t; k < KCB; k += 256) {
        float ncs = out[OFF_CS + k];
        g_cs[k] = __fmul_rn(__fdiv_rn(__fadd_rn(ncs, 1e-5f), denom), nf);
    }
    double ps = 0;
    for (int k = t; k < KCB; k += 256) {
        double p = (double)g_counts[k] / (double)NROWS;
        ps += p * log(p + 1e-10);
    }
    __syncthreads(); sd[t] = ps; __syncthreads();
    for (int o = 128; o; o >>= 1) { if (t < o) sd[t] += sd[t + o]; __syncthreads(); }
    if (!t) { out[OFF_LOSS] = (float)loss; out[OFF_PERP] = (float)exp(-sd[0]); }
}

// ---- EMA codebook update ----
__global__ __launch_bounds__(256) void k_emb(const float* __restrict__ emaw,
                                             float* __restrict__ out) {
    int e = blockIdx.x*256 + threadIdx.x;
    if (e >= KCB*DIM) return;
    int k = e >> 8;
    float ne = __fadd_rn(__fmul_rn(0.99f, emaw[e]), __fmul_rn(0.01f, g_dw[e]));
    out[OFF_EMA + e] = ne;
    out[OFF_EMB + e] = __fdiv_rn(ne, g_cs[k]);
}

extern "C" void kernel_launch(void* const* d_in, const int* in_sizes, int n_in,
                              void* d_out, int out_size) {
    const float* x    = (const float*)d_in[0];
    const float* w    = (const float*)d_in[1];
    const float* ecs  = (const float*)d_in[2];
    const float* emaw = (const float*)d_in[3];
    float* out = (float*)d_out;

    cudaFuncSetAttribute(k_mma_cand,
        cudaFuncAttributeMaxDynamicSharedMemorySize, SMEM_TOT);

    __nv_bfloat16 *xb, *wb;
    cudaGetSymbolAddress((void**)&xb, g_xb);
    cudaGetSymbolAddress((void**)&wb, g_wb);

    k_cast<<<NROWS*DIM/4/256, 256>>>(x, NROWS*DIM/4, xb);          // 1
    k_cast<<<KCB*DIM/4/256,   256>>>(w, KCB*DIM/4,   wb);          // 2
    k_rownorm_both<<<NROWS/8 + KCB/8, 256>>>(x, w);                // 3
    k_mma_cand<<<NROWS/128, 256, SMEM_TOT>>>();                    // 4  <- profiled slot
    k_rescore<<<NROWS/256, 256>>>(x, w);                           // 5
    k_count<<<NROWS/256, 256>>>();                                 // 6
    k_scan<<<1, 1024>>>();                                         // 7
    k_scatter<<<NROWS/256, 256>>>();                               // 8
    k_dw<<<KCB, 256>>>(x);                                         // 9
    k_quant<<<2048, 256>>>(x, w, out);                             // 10
    k_scalars<<<1, 256>>>(ecs, out);                               // 11
    k_emb<<<KCB*DIM/256, 256>>>(emaw, out);                        // 12
}

// round 13
// speedup vs baseline: 1.7073x; 1.6026x over previous
#include <cuda_runtime.h>
#include <cuda_bf16.h>
#include <math.h>

#define NROWS 65536
#define DIM   256
#define KCB   1024

#define OFF_LOSS 0
#define OFF_Q    1
#define OFF_PERP (1 + NROWS*DIM)
#define OFF_EMB  (OFF_PERP + 1)
#define OFF_CS   (OFF_EMB + KCB*DIM)
#define OFF_EMA  (OFF_CS + KCB)

__device__ float  g_A[NROWS];
__device__ float  g_C[KCB];
__device__ int    g_idx[NROWS];
__device__ int    g_cand[NROWS*3];
__device__ float  g_cd[NROWS*3];
__device__ float  g_counts[KCB];
__device__ float  g_dw[KCB*DIM];
__device__ float  g_cs[KCB];
__device__ double g_lp[2048];
__device__ int    g_ccount[KCB];
__device__ int    g_cursor[KCB];
__device__ int    g_off[KCB];
__device__ int    g_rows[NROWS];

__device__ __align__(16) __nv_bfloat16 g_xb[NROWS*DIM];
__device__ __align__(16) __nv_bfloat16 g_wb[KCB*DIM];

__device__ __forceinline__ unsigned smem_u32(const void* p) {
    unsigned a;
    asm("{ .reg .u64 t; cvta.to.shared.u64 t, %1; cvt.u32.u64 %0, t; }" : "=r"(a) : "l"(p));
    return a;
}
__device__ __forceinline__ int dless(float da, int ia, float db, int ib) {
    return (da < db) || (da == db && ia < ib);
}
#define CP_ASYNC16(dst, src) asm volatile("cp.async.cg.shared.global [%0], [%1], 16;" :: "r"(dst), "l"(src) : "memory")
#define CP_COMMIT()          asm volatile("cp.async.commit_group;" ::: "memory")
#define CP_WAIT(n)           asm volatile("cp.async.wait_group %0;" :: "n"(n) : "memory")
#define LDSM4(r0,r1,r2,r3,addr) \
    asm volatile("ldmatrix.sync.aligned.m8n8.x4.shared.b16 {%0,%1,%2,%3}, [%4];" \
        : "=r"(r0),"=r"(r1),"=r"(r2),"=r"(r3) : "r"(addr))

__device__ __forceinline__ void mma16816(float* c, const unsigned* a, unsigned b0, unsigned b1) {
    asm volatile("mma.sync.aligned.m16n8k16.row.col.f32.bf16.bf16.f32 "
        "{%0,%1,%2,%3}, {%4,%5,%6,%7}, {%8,%9}, {%0,%1,%2,%3};"
        : "+f"(c[0]), "+f"(c[1]), "+f"(c[2]), "+f"(c[3])
        : "r"(a[0]), "r"(a[1]), "r"(a[2]), "r"(a[3]), "r"(b0), "r"(b1));
}

// ---------------- fused cast + rownorm ----------------
__global__ __launch_bounds__(256) void k_prep(const float* __restrict__ src, int nrows,
                                              int which, __nv_bfloat16* __restrict__ dst) {
    int wd = threadIdx.x >> 5, l = threadIdx.x & 31;
    int row = blockIdx.x * 8 + wd;
    if (row >= nrows) return;
    const float4* r4 = (const float4*)(src + (size_t)row * DIM);
    float4 a = r4[l], b = r4[l + 32];
    ushort4 ua, ub;
    ua.x = __bfloat16_as_ushort(__float2bfloat16_rn(a.x));
    ua.y = __bfloat16_as_ushort(__float2bfloat16_rn(a.y));
    ua.z = __bfloat16_as_ushort(__float2bfloat16_rn(a.z));
    ua.w = __bfloat16_as_ushort(__float2bfloat16_rn(a.w));
    ub.x = __bfloat16_as_ushort(__float2bfloat16_rn(b.x));
    ub.y = __bfloat16_as_ushort(__float2bfloat16_rn(b.y));
    ub.z = __bfloat16_as_ushort(__float2bfloat16_rn(b.z));
    ub.w = __bfloat16_as_ushort(__float2bfloat16_rn(b.w));
    ushort4* d4 = (ushort4*)(dst + (size_t)row * DIM);
    d4[l] = ua; d4[l + 32] = ub;
    double s = (double)a.x*a.x + (double)a.y*a.y + (double)a.z*a.z + (double)a.w*a.w
             + (double)b.x*b.x + (double)b.y*b.y + (double)b.z*b.z + (double)b.w*b.w;
#pragma unroll
    for (int o = 16; o; o >>= 1) s += __shfl_down_sync(0xffffffffu, s, o);
    if (!l) { if (which) g_C[row] = (float)s; else g_A[row] = (float)s; }
}

// ---------------- raw-MMA distance GEMM -> global top-3 candidates ----------------
#define LDA 264
#define LDB 40
#define AS_BYTES (128*LDA*2)
#define BS_BYTES (128*LDB*2)
#define OFF_AS   0
#define OFF_BS   (AS_BYTES)
#define OFF_SC   (OFF_BS + 2*BS_BYTES)
#define OFF_MG   (OFF_SC + 4096)
#define SMEM_TOT (OFF_MG + 128*2*3*8)

__device__ __forceinline__ void prefetch_b(char* smem, int tid, int buf, int kc, int ct) {
    int code = tid >> 1, half = tid & 1;
    const __nv_bfloat16* src = g_wb + (size_t)(ct + code) * DIM + kc * 32 + half * 16;
    unsigned dst = smem_u32(smem + OFF_BS + buf * BS_BYTES + (code * LDB + half * 16) * 2);
    CP_ASYNC16(dst, src);
    CP_ASYNC16(dst + 16, src + 8);
    CP_COMMIT();
}

__global__ __launch_bounds__(256,2) void k_mma_cand() {
    extern __shared__ char smem[];
    __nv_bfloat16* As = (__nv_bfloat16*)(smem + OFF_AS);
    float* sC = (float*)(smem + OFF_SC);
    int tid = threadIdx.x, w = tid >> 5, lane = tid & 31;
    int rowBase = blockIdx.x * 128;
    int rw = w >> 1, cw = w & 1;
    int ql = lane >> 2, qc = lane & 3;

    for (int i = tid; i < KCB; i += 256) sC[i] = g_C[i];
    for (int u = tid; u < 128 * 32; u += 256) {
        int r = u >> 5, c8 = u & 31;
        *(uint4*)(As + r * LDA + c8 * 8) =
            *(const uint4*)(g_xb + (size_t)(rowBase + r) * DIM + c8 * 8);
    }
    __syncthreads();

    unsigned asb = smem_u32(As);
    unsigned bsb = smem_u32(smem + OFF_BS);

    float Ar[4];
#pragma unroll
    for (int rs = 0; rs < 4; rs++)
        Ar[rs] = g_A[rowBase + rw * 32 + (rs >> 1) * 16 + (rs & 1) * 8 + ql];

    float tD[4][3]; int tI[4][3];
#pragma unroll
    for (int rs = 0; rs < 4; rs++)
#pragma unroll
        for (int s = 0; s < 3; s++) { tD[rs][s] = 3.4e38f; tI[rs][s] = 0x7ffffff0 + s; }

    // ldmatrix lane address components
    int a_roff = ((lane >> 3) & 1) * 8 + (lane & 7);   // row within 16
    int a_koff = (lane >> 4) * 8;                      // k offset 0/8
    int b_noff = (lane >> 4) * 8 + (lane & 7);         // code within 16
    int b_koff = ((lane >> 3) & 1) * 8;                // k offset 0/8

    for (int ct8 = 0; ct8 < 8; ct8++) {
        int ct = ct8 * 128;
        float acc[2][8][4];
#pragma unroll
        for (int mt = 0; mt < 2; mt++)
#pragma unroll
            for (int nt = 0; nt < 8; nt++)
#pragma unroll
                for (int v = 0; v < 4; v++) acc[mt][nt][v] = 0.f;

        prefetch_b(smem, tid, 0, 0, ct);
        for (int kc = 0; kc < 8; kc++) {
            if (kc + 1 < 8) { prefetch_b(smem, tid, (kc + 1) & 1, kc + 1, ct); CP_WAIT(1); }
            else            { CP_WAIT(0); }
            __syncthreads();
            unsigned bb = bsb + (kc & 1) * BS_BYTES;
#pragma unroll
            for (int ks = 0; ks < 2; ks++) {
                int kcol = kc * 32 + ks * 16;      // A global k (A tile holds all 256 k)
                int bkcol = ks * 16;               // B chunk-local k (chunk holds 32 k)
                unsigned a[2][4];
#pragma unroll
                for (int mt = 0; mt < 2; mt++) {
                    unsigned addr = asb + ((rw * 32 + mt * 16 + a_roff) * LDA + kcol + a_koff) * 2;
                    LDSM4(a[mt][0], a[mt][1], a[mt][2], a[mt][3], addr);
                }
#pragma unroll
                for (int ng = 0; ng < 4; ng++) {
                    unsigned addr = bb + ((cw * 64 + ng * 16 + b_noff) * LDB + bkcol + b_koff) * 2;
                    unsigned b0, b1, b2, b3;
                    LDSM4(b0, b1, b2, b3, addr);
#pragma unroll
                    for (int mt = 0; mt < 2; mt++) {
                        mma16816(acc[mt][2 * ng],     a[mt], b0, b1);
                        mma16816(acc[mt][2 * ng + 1], a[mt], b2, b3);
                    }
                }
            }
            __syncthreads();
        }

        // register epilogue: distances + threshold-filtered top-3
#pragma unroll
        for (int mt = 0; mt < 2; mt++)
#pragma unroll
            for (int nt = 0; nt < 8; nt++) {
                int cb = ct + cw * 64 + nt * 8 + qc * 2;
#pragma unroll
                for (int v = 0; v < 4; v++) {
                    int rs = mt * 2 + (v >> 1);
                    int code = cb + (v & 1);
                    float d = __fadd_rn(__fsub_rn(Ar[rs], __fmul_rn(2.0f, acc[mt][nt][v])),
                                        sC[code]);
                    if (d < tD[rs][2]) {
                        if (d < tD[rs][0]) {
                            tD[rs][2] = tD[rs][1]; tI[rs][2] = tI[rs][1];
                            tD[rs][1] = tD[rs][0]; tI[rs][1] = tI[rs][0];
                            tD[rs][0] = d; tI[rs][0] = code;
                        } else if (d < tD[rs][1]) {
                            tD[rs][2] = tD[rs][1]; tI[rs][2] = tI[rs][1];
                            tD[rs][1] = d; tI[rs][1] = code;
                        } else {
                            tD[rs][2] = d; tI[rs][2] = code;
                        }
                    }
                }
            }
    }

    // merge the 4 lanes (qc 0..3) sharing each row: two xor-merge steps
#pragma unroll
    for (int rs = 0; rs < 4; rs++) {
#pragma unroll
        for (int step = 1; step <= 2; step++) {
            float md[6]; int mi[6];
#pragma unroll
            for (int s = 0; s < 3; s++) {
                md[s] = tD[rs][s]; mi[s] = tI[rs][s];
                md[3 + s] = __shfl_xor_sync(0xffffffffu, tD[rs][s], step);
                mi[3 + s] = __shfl_xor_sync(0xffffffffu, tI[rs][s], step);
            }
#pragma unroll
            for (int p = 0; p < 3; p++)
#pragma unroll
                for (int q = p + 1; q < 6; q++)
                    if (dless(md[q], mi[q], md[p], mi[p])) {
                        float td = md[p]; md[p] = md[q]; md[q] = td;
                        int   ti = mi[p]; mi[p] = mi[q]; mi[q] = ti;
                    }
#pragma unroll
            for (int s = 0; s < 3; s++) { tD[rs][s] = md[s]; tI[rs][s] = mi[s]; }
        }
    }

    float* mD = (float*)(smem + OFF_MG);
    int*   mI = (int*)(smem + OFF_MG + 128 * 2 * 3 * 4);
    if (qc == 0) {
#pragma unroll
        for (int rs = 0; rs < 4; rs++) {
            int rloc = rw * 32 + (rs >> 1) * 16 + (rs & 1) * 8 + ql;
#pragma unroll
            for (int s = 0; s < 3; s++) {
                mD[(rloc * 2 + cw) * 3 + s] = tD[rs][s];
                mI[(rloc * 2 + cw) * 3 + s] = tI[rs][s];
            }
        }
    }
    __syncthreads();
    if (tid < 128) {
        float md[6]; int mi[6];
#pragma unroll
        for (int s = 0; s < 3; s++) {
            md[s]     = mD[(tid * 2 + 0) * 3 + s]; mi[s]     = mI[(tid * 2 + 0) * 3 + s];
            md[3 + s] = mD[(tid * 2 + 1) * 3 + s]; mi[3 + s] = mI[(tid * 2 + 1) * 3 + s];
        }
#pragma unroll
        for (int p = 0; p < 3; p++)
#pragma unroll
            for (int q = p + 1; q < 6; q++)
                if (dless(md[q], mi[q], md[p], mi[p])) {
                    float td = md[p]; md[p] = md[q]; md[q] = td;
                    int   ti = mi[p]; mi[p] = mi[q]; mi[q] = ti;
                }
        int row = rowBase + tid;
#pragma unroll
        for (int s = 0; s < 3; s++) {
            g_cand[row * 3 + s] = mi[s];
            g_cd[row * 3 + s]   = md[s];
        }
    }
}

// ---------------- margin-gated exact rescore (R3 SIMT chain) ----------------
#define MARGIN 1.5e-3f
__global__ __launch_bounds__(256) void k_rescore(const float* __restrict__ x,
                                                 const float* __restrict__ w) {
    int row = blockIdx.x * 256 + threadIdx.x;
    if (row >= NROWS) return;
    if (row < KCB) { g_ccount[row] = 0; g_cursor[row] = 0; }
    int c0 = g_cand[row * 3], c1 = g_cand[row * 3 + 1], c2 = g_cand[row * 3 + 2];
    float d0 = g_cd[row * 3], d1 = g_cd[row * 3 + 1];
    if (__fsub_rn(d1, d0) > MARGIN) { g_idx[row] = c0; return; }
    int c[3] = { c0, c1, c2 };
    const float4* xr = (const float4*)(x + (size_t)row * DIM);
    const float4* wr[3];
#pragma unroll
    for (int s = 0; s < 3; s++) wr[s] = (const float4*)(w + (size_t)c[s] * DIM);
    float dot[3] = { 0.f, 0.f, 0.f };
#pragma unroll 4
    for (int k4 = 0; k4 < 64; k4++) {
        float4 xv = xr[k4];
#pragma unroll
        for (int s = 0; s < 3; s++) {
            float4 wv = wr[s][k4];
            dot[s] = __fmaf_rn(xv.x, wv.x, dot[s]);
            dot[s] = __fmaf_rn(xv.y, wv.y, dot[s]);
            dot[s] = __fmaf_rn(xv.z, wv.z, dot[s]);
            dot[s] = __fmaf_rn(xv.w, wv.w, dot[s]);
        }
    }
    float A = g_A[row];
    float bd = 3.4e38f; int bi = 0x7fffffff;
#pragma unroll
    for (int s = 0; s < 3; s++) {
        float d = __fadd_rn(__fsub_rn(A, __fmul_rn(2.0f, dot[s])), g_C[c[s]]);
        if (dless(d, c[s], bd, bi)) { bd = d; bi = c[s]; }
    }
    g_idx[row] = bi;
}

// ---- bucket pipeline: histogram -> scan -> scatter -> dw gather ----
__global__ __launch_bounds__(256) void k_count() {
    int i = blockIdx.x * 256 + threadIdx.x;
    if (i < NROWS) atomicAdd(&g_ccount[g_idx[i]], 1);
}

__global__ __launch_bounds__(1024) void k_scan() {
    __shared__ int sh[1024];
    int t = threadIdx.x;
    int v = g_ccount[t];
    sh[t] = v;
    __syncthreads();
    int sum = v;
    for (int o = 1; o < 1024; o <<= 1) {
        int add = (t >= o) ? sh[t - o] : 0;
        __syncthreads();
        sh[t] = sum = sum + add;
        __syncthreads();
    }
    g_off[t] = sum - v;
    g_counts[t] = (float)v;
}

__global__ __launch_bounds__(256) void k_scatter() {
    int i = blockIdx.x * 256 + threadIdx.x;
    if (i >= NROWS) return;
    int k = g_idx[i];
    int pos = atomicAdd(&g_cursor[k], 1);
    g_rows[g_off[k] + pos] = i;
}

__global__ __launch_bounds__(256) void k_dw(const float* __restrict__ x) {
    int k = blockIdx.x, d = threadIdx.x;
    int off = g_off[k], m = g_ccount[k];
    float a0 = 0.f, a1 = 0.f;
    int j = 0;
    for (; j + 1 < m; j += 2) {
        a0 += x[(size_t)g_rows[off + j] * DIM + d];
        a1 += x[(size_t)g_rows[off + j + 1] * DIM + d];
    }
    if (j < m) a0 += x[(size_t)g_rows[off + j] * DIM + d];
    g_dw[k * DIM + d] = a0 + a1;
}

// ---- gather codebook, STE output, loss partials ----
__global__ __launch_bounds__(256) void k_quant(const float* __restrict__ x,
                                               const float* __restrict__ w,
                                               float* __restrict__ out) {
    __shared__ double sr[256];
    double ls = 0.0;
    int stride = gridDim.x * 256;
    for (int e4 = blockIdx.x*256 + threadIdx.x; e4 < NROWS*DIM/4; e4 += stride) {
        int row = e4 >> 6, c4 = e4 & 63;
        int k = g_idx[row];
        float4 xv = ((const float4*)x)[e4];
        float4 qv = ((const float4*)w)[k*64 + c4];
        float d0 = __fsub_rn(qv.x, xv.x), d1 = __fsub_rn(qv.y, xv.y);
        float d2 = __fsub_rn(qv.z, xv.z), d3 = __fsub_rn(qv.w, xv.w);
        float* o = out + OFF_Q + (size_t)e4*4;
        o[0] = __fadd_rn(xv.x, d0); o[1] = __fadd_rn(xv.y, d1);
        o[2] = __fadd_rn(xv.z, d2); o[3] = __fadd_rn(xv.w, d3);
        float s4 = __fmaf_rn(d0, d0, __fmaf_rn(d1, d1, __fmaf_rn(d2, d2, d3*d3)));
        ls += (double)s4;
    }
    sr[threadIdx.x] = ls;
    __syncthreads();
    for (int o = 128; o; o >>= 1) { if (threadIdx.x < o) sr[threadIdx.x] += sr[threadIdx.x + o]; __syncthreads(); }
    if (!threadIdx.x) g_lp[blockIdx.x] = sr[0];
}

// ---- scalars ----
__global__ __launch_bounds__(256) void k_scalars(const float* __restrict__ ecs,
                                                 float* __restrict__ out) {
    __shared__ double sd[256];
    int t = threadIdx.x;
    double s = 0;
    for (int i = t; i < 2048; i += 256) s += g_lp[i];
    sd[t] = s; __syncthreads();
    for (int o = 128; o; o >>= 1) { if (t < o) sd[t] += sd[t + o]; __syncthreads(); }
    double loss = 0.25 * sd[0] / ((double)NROWS * DIM);
    double ns = 0;
    for (int k = t; k < KCB; k += 256) {
        float ncs = __fadd_rn(__fmul_rn(0.99f, ecs[k]), __fmul_rn(0.01f, g_counts[k]));
        out[OFF_CS + k] = ncs;
        ns += ncs;
    }
    __syncthreads(); sd[t] = ns; __syncthreads();
    for (int o = 128; o; o >>= 1) { if (t < o) sd[t] += sd[t + o]; __syncthreads(); }
    float nf = (float)sd[0];
    float denom = __fadd_rn(nf, (float)(1024.0 * 1e-5));
    for (int k = t; k < KCB; k += 256) {
        float ncs = out[OFF_CS + k];
        g_cs[k] = __fmul_rn(__fdiv_rn(__fadd_rn(ncs, 1e-5f), denom), nf);
    }
    double ps = 0;
    for (int k = t; k < KCB; k += 256) {
        double p = (double)g_counts[k] / (double)NROWS;
        ps += p * log(p + 1e-10);
    }
    __syncthreads(); sd[t] = ps; __syncthreads();
    for (int o = 128; o; o >>= 1) { if (t < o) sd[t] += sd[t + o]; __syncthreads(); }
    if (!t) { out[OFF_LOSS] = (float)loss; out[OFF_PERP] = (float)exp(-sd[0]); }
}

// ---- EMA codebook update ----
__global__ __launch_bounds__(256) void k_emb(const float* __restrict__ emaw,
                                             float* __restrict__ out) {
    int e = blockIdx.x*256 + threadIdx.x;
    if (e >= KCB*DIM) return;
    int k = e >> 8;
    float ne = __fadd_rn(__fmul_rn(0.99f, emaw[e]), __fmul_rn(0.01f, g_dw[e]));
    out[OFF_EMA + e] = ne;
    out[OFF_EMB + e] = __fdiv_rn(ne, g_cs[k]);
}

extern "C" void kernel_launch(void* const* d_in, const int* in_sizes, int n_in,
                              void* d_out, int out_size) {
    const float* x    = (const float*)d_in[0];
    const float* w    = (const float*)d_in[1];
    const float* ecs  = (const float*)d_in[2];
    const float* emaw = (const float*)d_in[3];
    float* out = (float*)d_out;

    cudaFuncSetAttribute(k_mma_cand,
        cudaFuncAttributeMaxDynamicSharedMemorySize, SMEM_TOT);

    __nv_bfloat16 *xb, *wb;
    cudaGetSymbolAddress((void**)&xb, g_xb);
    cudaGetSymbolAddress((void**)&wb, g_wb);

    k_prep<<<NROWS/8, 256>>>(x, NROWS, 0, xb);       // 1
    k_prep<<<KCB/8,   256>>>(w, KCB,   1, wb);       // 2
    k_mma_cand<<<NROWS/128, 256, SMEM_TOT>>>();      // 3
    k_rescore<<<NROWS/256, 256>>>(x, w);             // 4 <- profiled slot
    k_count<<<NROWS/256, 256>>>();                   // 5
    k_scan<<<1, 1024>>>();                           // 6
    k_scatter<<<NROWS/256, 256>>>();                 // 7
    k_dw<<<KCB, 256>>>(x);                           // 8
    k_quant<<<2048, 256>>>(x, w, out);               // 9
    k_scalars<<<1, 256>>>(ecs, out);                 // 10
    k_emb<<<KCB*DIM/256, 256>>>(emaw, out);          // 11
}